// round 5
// baseline (speedup 1.0000x reference)
#include <cuda_runtime.h>

// Problem constants
#define NSEQ    32768      // B*A = 256*128
#define TSTEPS  50
#define NI      16
#define NH      128
#define NG      512        // 4*NH
#define NK      144        // NI + NH
#define SPB     32         // sequences per block
#define THREADS 256
#define KT      16         // k-rows per W slab
#define NSLAB   9          // NK / KT
#define CO      (NSEQ * NH)   // offset of c in output

// Pre-transposed combined weights: g_Wt[k][g], k in [0,144): rows 0..15 = W_ih^T, 16..143 = W_hh^T
// 16B alignment is REQUIRED: g_Wt is the source of cp.async.cg 16-byte copies.
__device__ __align__(16) float g_Wt[NK * NG];
__device__ __align__(16) float g_bias[NG];

__global__ void prep_kernel(const float* __restrict__ W_ih, const float* __restrict__ W_hh,
                            const float* __restrict__ b_ih, const float* __restrict__ b_hh) {
    int tid = blockIdx.x * blockDim.x + threadIdx.x;
    int stride = gridDim.x * blockDim.x;
    for (int idx = tid; idx < NG * NI; idx += stride) {
        int g = idx / NI, k = idx % NI;
        g_Wt[k * NG + g] = W_ih[idx];
    }
    for (int idx = tid; idx < NG * NH; idx += stride) {
        int g = idx / NH, k = idx % NH;
        g_Wt[(NI + k) * NG + g] = W_hh[idx];
    }
    for (int idx = tid; idx < NG; idx += stride) g_bias[idx] = b_ih[idx] + b_hh[idx];
}

// ---- packed f32x2 helpers ----
__device__ __forceinline__ unsigned long long pack2(float lo, float hi) {
    unsigned long long r;
    asm("mov.b64 %0, {%1, %2};" : "=l"(r) : "f"(lo), "f"(hi));
    return r;
}
__device__ __forceinline__ void unpack2(unsigned long long v, float& lo, float& hi) {
    asm("mov.b64 {%0, %1}, %2;" : "=f"(lo), "=f"(hi) : "l"(v));
}
__device__ __forceinline__ void ffma2(unsigned long long& d, unsigned long long a, unsigned long long b) {
    asm("fma.rn.f32x2 %0, %1, %2, %0;" : "+l"(d) : "l"(a), "l"(b));
}

// ---- cp.async helpers ----
__device__ __forceinline__ void cpasync16(void* smem_ptr, const void* gptr) {
    unsigned saddr = (unsigned)__cvta_generic_to_shared(smem_ptr);
    asm volatile("cp.async.cg.shared.global [%0], [%1], 16;" :: "r"(saddr), "l"(gptr));
}
#define CP_COMMIT() asm volatile("cp.async.commit_group;" ::: "memory")
#define CP_WAIT0()  asm volatile("cp.async.wait_group 0;" ::: "memory")

__device__ __forceinline__ float sigf(float x) {
    return __fdividef(1.0f, 1.0f + __expf(-x));
}
__device__ __forceinline__ float tanhfast(float x) {
    // 2*sigmoid(2x) - 1; graceful saturation at both extremes
    return 2.0f * sigf(2.0f * x) - 1.0f;
}

// Shared memory layout (floats):
//   xh  [NK][SPB]     : rows 0..15 = x_t (transposed), rows 16..143 = h state. 4608 floats
//   Wsh [2][KT][NG]   : double-buffered weight slabs.                        16384 floats
#define XH_OFF 0
#define W_OFF  4608
#define SMEM_FLOATS (4608 + 2 * 8192)
#define SMEM_BYTES (SMEM_FLOATS * 4)

__global__ void __launch_bounds__(THREADS)
lstm_kernel(const float* __restrict__ seq, const float* __restrict__ mask,
            float* __restrict__ out) {
    extern __shared__ __align__(16) float sm[];
    float* xh  = sm + XH_OFF;    // [144][32]
    float* Wsh = sm + W_OFF;     // [2][16][512]

    const int tid  = threadIdx.x;
    const int st   = tid & 7;    // seq tile: seqs st*4 .. st*4+3
    const int ht   = tid >> 3;   // 0..31, h-units ht*4 .. ht*4+3
    const int seq0 = blockIdx.x * SPB;

    // Prefetch slab 0 into buffer 0 (overlaps with init below)
    {
        const float4* src = (const float4*)(g_Wt);
#pragma unroll
        for (int r = 0; r < (KT * NG / 4) / THREADS; r++)
            cpasync16(Wsh + 4 * (tid + r * THREADS), src + tid + r * THREADS);
        CP_COMMIT();
    }

    // Per-thread bias registers: bias_r[gate_type][j] for hu = ht*4+j
    float bias_r[4][4];
#pragma unroll
    for (int g = 0; g < 4; g++)
#pragma unroll
        for (int j = 0; j < 4; j++)
            bias_r[g][j] = g_bias[g * NH + ht * 4 + j];

    // Zero h rows of xh (h0 = 0)
    for (int i = tid; i < NH * SPB; i += THREADS) xh[NI * SPB + i] = 0.0f;

    // c state in registers: c[j][s], j = hu offset 0..3, s = seq offset 0..3
    float c[4][4];
#pragma unroll
    for (int j = 0; j < 4; j++)
#pragma unroll
        for (int s = 0; s < 4; s++) c[j][s] = 0.0f;

    CP_WAIT0();
    __syncthreads();   // slab 0 resident; h rows zeroed

    int cur = 0;       // current W buffer index

    for (int t = 0; t < TSTEPS; t++) {
        // ---- load x_t into xh rows 0..15 (transposed: xh[i][s]) ----
        {
            int i = tid & 15;
            int s = tid >> 4;  // 0..15
            xh[i * SPB + s]      = seq[((seq0 + s)      * TSTEPS + t) * NI + i];
            xh[i * SPB + s + 16] = seq[((seq0 + s + 16) * TSTEPS + t) * NI + i];
        }
        __syncthreads();  // publish x rows (+ h rows from previous step's pointwise)

        // ---- accumulate gates over 9 weight slabs (double-buffered) ----
        unsigned long long acc[4][2][4];  // [gate_type][hu pair][seq]
#pragma unroll
        for (int g = 0; g < 4; g++)
#pragma unroll
            for (int jp = 0; jp < 2; jp++)
#pragma unroll
                for (int s = 0; s < 4; s++) acc[g][jp][s] = 0ULL;

        for (int kt = 0; kt < NSLAB; kt++) {
            // prefetch next slab into the other buffer (wraps to slab 0 for next step).
            // Safe: the buffer cur^1 was last READ in iteration kt-1, which ended
            // with a __syncthreads after all reads.
            {
                const int sl_next = (kt + 1 == NSLAB) ? 0 : kt + 1;
                const float4* src = (const float4*)(g_Wt + sl_next * (KT * NG));
                float* dst = Wsh + (cur ^ 1) * (KT * NG);
#pragma unroll
                for (int r = 0; r < (KT * NG / 4) / THREADS; r++)
                    cpasync16(dst + 4 * (tid + r * THREADS), src + tid + r * THREADS);
                CP_COMMIT();
            }

            const float* Wb = Wsh + cur * (KT * NG);
#pragma unroll
            for (int kk = 0; kk < KT; kk++) {
                const int k = kt * KT + kk;
                const float4 hv = ((const float4*)(xh + k * SPB))[st];
                const unsigned long long hp0 = pack2(hv.x, hv.x);
                const unsigned long long hp1 = pack2(hv.y, hv.y);
                const unsigned long long hp2 = pack2(hv.z, hv.z);
                const unsigned long long hp3 = pack2(hv.w, hv.w);
#pragma unroll
                for (int g = 0; g < 4; g++) {
                    const ulonglong2 w2 =
                        *((const ulonglong2*)(Wb + kk * NG + g * NH + ht * 4));
                    ffma2(acc[g][0][0], w2.x, hp0);
                    ffma2(acc[g][0][1], w2.x, hp1);
                    ffma2(acc[g][0][2], w2.x, hp2);
                    ffma2(acc[g][0][3], w2.x, hp3);
                    ffma2(acc[g][1][0], w2.y, hp0);
                    ffma2(acc[g][1][1], w2.y, hp1);
                    ffma2(acc[g][1][2], w2.y, hp2);
                    ffma2(acc[g][1][3], w2.y, hp3);
                }
            }

            CP_WAIT0();       // next slab's data landed (this thread's copies)
            __syncthreads();  // all threads done reading cur buffer & all copies visible
            cur ^= 1;
        }
        // NOTE: the kt-loop's final __syncthreads also guarantees every thread has
        // finished reading xh for this step, so pointwise h-row writes below are safe.

        // ---- pointwise LSTM update (each thread owns its 16 (hu, seq) cells) ----
#pragma unroll
        for (int s = 0; s < 4; s++) {
            const int sq = st * 4 + s;
            const float m = mask[(seq0 + sq) * TSTEPS + t];
#pragma unroll
            for (int jp = 0; jp < 2; jp++) {
                float iv0, iv1, fv0, fv1, gv0, gv1, ov0, ov1;
                unpack2(acc[0][jp][s], iv0, iv1);
                unpack2(acc[1][jp][s], fv0, fv1);
                unpack2(acc[2][jp][s], gv0, gv1);
                unpack2(acc[3][jp][s], ov0, ov1);
#pragma unroll
                for (int u = 0; u < 2; u++) {
                    const int j = jp * 2 + u;
                    const float ig = (u == 0) ? iv0 : iv1;
                    const float fg = (u == 0) ? fv0 : fv1;
                    const float gg = (u == 0) ? gv0 : gv1;
                    const float og = (u == 0) ? ov0 : ov1;
                    const float i_a = sigf(ig + bias_r[0][j]);
                    const float f_a = sigf(fg + bias_r[1][j]);
                    const float g_a = tanhfast(gg + bias_r[2][j]);
                    const float o_a = sigf(og + bias_r[3][j]);
                    const float cn = f_a * c[j][s] + i_a * g_a;
                    const float hn = o_a * tanhfast(cn);
                    c[j][s] = m * (cn - c[j][s]) + c[j][s];
                    const int hu = ht * 4 + j;
                    float* hp = &xh[(NI + hu) * SPB + sq];
                    const float hold = *hp;
                    *hp = m * (hn - hold) + hold;
                }
            }
        }
        // next iteration's top-of-step __syncthreads publishes the new h rows
    }

    __syncthreads();  // final h values visible to all threads

    // ---- write h (coalesced cooperative copy from xh) ----
    for (int idx = tid; idx < SPB * NH; idx += THREADS) {
        const int s  = idx >> 7;    // / NH
        const int hu = idx & (NH - 1);
        out[(seq0 + s) * NH + hu] = xh[(NI + hu) * SPB + s];
    }
    // ---- write c from registers (float4 over contiguous hu) ----
#pragma unroll
    for (int s = 0; s < 4; s++) {
        const int sq = st * 4 + s;
        float4 cv = make_float4(c[0][s], c[1][s], c[2][s], c[3][s]);
        *(float4*)(out + CO + (seq0 + sq) * NH + ht * 4) = cv;
    }
}

extern "C" void kernel_launch(void* const* d_in, const int* in_sizes, int n_in,
                              void* d_out, int out_size) {
    const float* seq_p  = (const float*)d_in[0];
    const float* mask_p = (const float*)d_in[1];
    const float* W_ih   = (const float*)d_in[2];
    const float* W_hh   = (const float*)d_in[3];
    const float* b_ih   = (const float*)d_in[4];
    const float* b_hh   = (const float*)d_in[5];
    float* out = (float*)d_out;

    prep_kernel<<<64, 256>>>(W_ih, W_hh, b_ih, b_hh);

    cudaFuncSetAttribute(lstm_kernel, cudaFuncAttributeMaxDynamicSharedMemorySize, SMEM_BYTES);
    lstm_kernel<<<NSEQ / SPB, THREADS, SMEM_BYTES>>>(seq_p, mask_p, out);
}

// round 17
// speedup vs baseline: 1.0511x; 1.0511x over previous
#include <cuda_runtime.h>

// Problem constants
#define NSEQ    32768      // B*A = 256*128
#define TSTEPS  50
#define NI      16
#define NH      128
#define NG      512        // 4*NH
#define NK      144        // NI + NH
#define SPB     64         // sequences per block
#define XSTR    64         // xh row stride (unpadded: pointwise I/O is vectorized instead)
#define THREADS 256
#define KT      16         // k-rows per W slab
#define NSLAB   9          // NK / KT
#define CO      (NSEQ * NH)   // offset of c in output

// Pre-transposed combined weights: g_Wt[k][g], k in [0,144): rows 0..15 = W_ih^T, 16..143 = W_hh^T
// 16B alignment REQUIRED: g_Wt is the source of cp.async.cg 16-byte copies.
__device__ __align__(16) float g_Wt[NK * NG];
__device__ __align__(16) float g_bias[NG];

__global__ void prep_kernel(const float* __restrict__ W_ih, const float* __restrict__ W_hh,
                            const float* __restrict__ b_ih, const float* __restrict__ b_hh) {
    int tid = blockIdx.x * blockDim.x + threadIdx.x;
    int stride = gridDim.x * blockDim.x;
    for (int idx = tid; idx < NG * NI; idx += stride) {
        int g = idx / NI, k = idx % NI;
        g_Wt[k * NG + g] = W_ih[idx];
    }
    for (int idx = tid; idx < NG * NH; idx += stride) {
        int g = idx / NH, k = idx % NH;
        g_Wt[(NI + k) * NG + g] = W_hh[idx];
    }
    for (int idx = tid; idx < NG; idx += stride) g_bias[idx] = b_ih[idx] + b_hh[idx];
}

// ---- packed f32x2 helpers ----
__device__ __forceinline__ unsigned long long pack2(float lo, float hi) {
    unsigned long long r;
    asm("mov.b64 %0, {%1, %2};" : "=l"(r) : "f"(lo), "f"(hi));
    return r;
}
__device__ __forceinline__ void unpack2(unsigned long long v, float& lo, float& hi) {
    asm("mov.b64 {%0, %1}, %2;" : "=f"(lo), "=f"(hi) : "l"(v));
}
__device__ __forceinline__ void ffma2(unsigned long long& d, unsigned long long a, unsigned long long b) {
    asm("fma.rn.f32x2 %0, %1, %2, %0;" : "+l"(d) : "l"(a), "l"(b));
}

// ---- cp.async helpers ----
__device__ __forceinline__ void cpasync16(void* smem_ptr, const void* gptr) {
    unsigned saddr = (unsigned)__cvta_generic_to_shared(smem_ptr);
    asm volatile("cp.async.cg.shared.global [%0], [%1], 16;" :: "r"(saddr), "l"(gptr));
}
#define CP_COMMIT() asm volatile("cp.async.commit_group;" ::: "memory")
#define CP_WAIT0()  asm volatile("cp.async.wait_group 0;" ::: "memory")

// ---- activations via MUFU.TANH (1 MUFU each) ----
__device__ __forceinline__ float tanhf_a(float x) {
    float t;
    asm("tanh.approx.f32 %0, %1;" : "=f"(t) : "f"(x));
    return t;
}
__device__ __forceinline__ float sigf(float x) {
    return 0.5f * tanhf_a(0.5f * x) + 0.5f;
}

// Shared memory layout (floats):
//   xh   [NK][64]      rows 0..15 = x_t (transposed), rows 16..143 = h state : 9216
//   bsm  [NG]          combined bias                                         : 512
//   Wsh  [2][KT][NG]   double-buffered weight slabs                          : 16384
#define XH_OFF 0
#define B_OFF  (NK * XSTR)            // 9216
#define W_OFF  (B_OFF + NG)           // 9728
#define SMEM_FLOATS (W_OFF + 2 * KT * NG)
#define SMEM_BYTES (SMEM_FLOATS * 4)  // 104448 B

__global__ void __launch_bounds__(THREADS)
lstm_kernel(const float* __restrict__ seq, const float* __restrict__ mask,
            float* __restrict__ out) {
    extern __shared__ __align__(16) float sm[];
    float* xh  = sm + XH_OFF;    // [144][64]
    float* bsm = sm + B_OFF;     // [512]
    float* Wsh = sm + W_OFF;     // [2][16][512]

    const int tid  = threadIdx.x;
    const int st   = tid & 7;    // seq tile: seqs st*8 .. st*8+7
    const int ht   = tid >> 3;   // 0..31, h-units ht*4 .. ht*4+3
    const int seq0 = blockIdx.x * SPB;
    const int xs   = tid >> 2;   // x-staging: seq index 0..63
    const int xi4  = tid & 3;    // x-staging: feature quad 0..3

    // Prefetch W slab 0 into buffer 0 (overlaps init below)
    {
        const float4* src = (const float4*)(g_Wt);
#pragma unroll
        for (int r = 0; r < (KT * NG / 4) / THREADS; r++)
            cpasync16(Wsh + 4 * (tid + r * THREADS), src + tid + r * THREADS);
        CP_COMMIT();
    }

    // Preload x(t=0) into registers (stored to smem at top of step 0)
    float4 xv = *(const float4*)(seq + ((size_t)(seq0 + xs) * TSTEPS + 0) * NI + xi4 * 4);

    // Bias into smem
    for (int i = tid; i < NG; i += THREADS) bsm[i] = g_bias[i];

    // Zero h rows of xh (h0 = 0)
    for (int i = tid; i < NH * XSTR; i += THREADS) xh[NI * XSTR + i] = 0.0f;

    // c state in registers: c[j][s], j = hu offset 0..3, s = seq offset 0..7
    float c[4][8];
#pragma unroll
    for (int j = 0; j < 4; j++)
#pragma unroll
        for (int s = 0; s < 8; s++) c[j][s] = 0.0f;

    CP_WAIT0();
    __syncthreads();   // slab 0 resident; h rows zeroed; bias staged

    int cur = 0;       // current W buffer index

    for (int t = 0; t < TSTEPS; t++) {
        // ---- store x(t) (already in regs) transposed into xh rows 0..15 ----
        xh[(xi4 * 4 + 0) * XSTR + xs] = xv.x;
        xh[(xi4 * 4 + 1) * XSTR + xs] = xv.y;
        xh[(xi4 * 4 + 2) * XSTR + xs] = xv.z;
        xh[(xi4 * 4 + 3) * XSTR + xs] = xv.w;
        __syncthreads();  // publish x(t) rows + h rows written by prev pointwise

        // ---- prefetch x(t+1) into regs (latency hidden behind the mainloop) ----
        if (t + 1 < TSTEPS)
            xv = *(const float4*)(seq + ((size_t)(seq0 + xs) * TSTEPS + (t + 1)) * NI + xi4 * 4);

        // ---- mask(t) for this thread's 8 seqs (consumed in pointwise; hidden) ----
        float mregs[8];
#pragma unroll
        for (int s = 0; s < 8; s++)
            mregs[s] = mask[(size_t)(seq0 + st * 8 + s) * TSTEPS + t];

        // ---- init accumulators with bias (packed pairs) ----
        unsigned long long acc[4][2][8];  // [gate][hu pair][seq]
#pragma unroll
        for (int g = 0; g < 4; g++) {
            const ulonglong2 b2 = *((const ulonglong2*)(bsm + g * NH + ht * 4));
#pragma unroll
            for (int s = 0; s < 8; s++) { acc[g][0][s] = b2.x; acc[g][1][s] = b2.y; }
        }

        for (int kt = 0; kt < NSLAB; kt++) {
            // prefetch next slab into the other buffer (wraps to slab 0 for next step)
            {
                const int sl_next = (kt + 1 == NSLAB) ? 0 : kt + 1;
                const float4* src = (const float4*)(g_Wt + sl_next * (KT * NG));
                float* dst = Wsh + (cur ^ 1) * (KT * NG);
#pragma unroll
                for (int r = 0; r < (KT * NG / 4) / THREADS; r++)
                    cpasync16(dst + 4 * (tid + r * THREADS), src + tid + r * THREADS);
                CP_COMMIT();
            }

            const float* Wb = Wsh + cur * (KT * NG);
#pragma unroll 8
            for (int kk = 0; kk < KT; kk++) {
                const int k = kt * KT + kk;
                const float* xrow = xh + k * XSTR + st * 8;   // 16B-aligned (stride 64)
                const float4 ha = *(const float4*)(xrow);
                const float4 hb = *(const float4*)(xrow + 4);
                unsigned long long hp[8];
                hp[0] = pack2(ha.x, ha.x); hp[1] = pack2(ha.y, ha.y);
                hp[2] = pack2(ha.z, ha.z); hp[3] = pack2(ha.w, ha.w);
                hp[4] = pack2(hb.x, hb.x); hp[5] = pack2(hb.y, hb.y);
                hp[6] = pack2(hb.z, hb.z); hp[7] = pack2(hb.w, hb.w);
#pragma unroll
                for (int g = 0; g < 4; g++) {
                    const ulonglong2 w2 =
                        *((const ulonglong2*)(Wb + kk * NG + g * NH + ht * 4));
#pragma unroll
                    for (int s = 0; s < 8; s++) {
                        ffma2(acc[g][0][s], w2.x, hp[s]);
                        ffma2(acc[g][1][s], w2.y, hp[s]);
                    }
                }
            }

            CP_WAIT0();       // next slab landed (this thread's copies)
            __syncthreads();  // all threads done reading cur buffer; copies visible
            cur ^= 1;
        }
        // kt-loop's final __syncthreads also fences all xh reads of this step,
        // so the pointwise h-row writes below are safe.

        // ---- pointwise LSTM update: vectorized h I/O (LDS.128 / STS.128) ----
#pragma unroll
        for (int jp = 0; jp < 2; jp++) {
            const int j0 = jp * 2, j1 = jp * 2 + 1;
            float* hrow0 = &xh[(NI + ht * 4 + j0) * XSTR + st * 8];
            float* hrow1 = &xh[(NI + ht * 4 + j1) * XSTR + st * 8];
            float old0[8], old1[8], hn0[8], hn1[8];
            *(float4*)(old0)     = *(const float4*)(hrow0);
            *(float4*)(old0 + 4) = *(const float4*)(hrow0 + 4);
            *(float4*)(old1)     = *(const float4*)(hrow1);
            *(float4*)(old1 + 4) = *(const float4*)(hrow1 + 4);
#pragma unroll
            for (int s = 0; s < 8; s++) {
                const float m = mregs[s];
                float iv0, iv1, fv0, fv1, gv0, gv1, ov0, ov1;
                unpack2(acc[0][jp][s], iv0, iv1);
                unpack2(acc[1][jp][s], fv0, fv1);
                unpack2(acc[2][jp][s], gv0, gv1);
                unpack2(acc[3][jp][s], ov0, ov1);
                // lane 0 of the pair -> j0
                {
                    const float i_a = sigf(iv0), f_a = sigf(fv0);
                    const float g_a = tanhf_a(gv0), o_a = sigf(ov0);
                    const float cn = f_a * c[j0][s] + i_a * g_a;
                    const float hn = o_a * tanhf_a(cn);
                    c[j0][s] = m * (cn - c[j0][s]) + c[j0][s];
                    hn0[s] = m * (hn - old0[s]) + old0[s];
                }
                // lane 1 of the pair -> j1
                {
                    const float i_a = sigf(iv1), f_a = sigf(fv1);
                    const float g_a = tanhf_a(gv1), o_a = sigf(ov1);
                    const float cn = f_a * c[j1][s] + i_a * g_a;
                    const float hn = o_a * tanhf_a(cn);
                    c[j1][s] = m * (cn - c[j1][s]) + c[j1][s];
                    hn1[s] = m * (hn - old1[s]) + old1[s];
                }
            }
            *(float4*)(hrow0)     = *(const float4*)(hn0);
            *(float4*)(hrow0 + 4) = *(const float4*)(hn0 + 4);
            *(float4*)(hrow1)     = *(const float4*)(hn1);
            *(float4*)(hrow1 + 4) = *(const float4*)(hn1 + 4);
        }
        // next iteration's top-of-step __syncthreads publishes the new h rows
    }

    __syncthreads();  // final h values visible to all threads

    // ---- write h (coalesced gmem; smem reads are a one-time cost) ----
    for (int idx = tid; idx < SPB * NH; idx += THREADS) {
        const int s  = idx >> 7;    // / NH
        const int hu = idx & (NH - 1);
        out[(size_t)(seq0 + s) * NH + hu] = xh[(NI + hu) * XSTR + s];
    }
    // ---- write c from registers (float4 over contiguous hu) ----
#pragma unroll
    for (int s = 0; s < 8; s++) {
        const int sq = st * 8 + s;
        float4 cv = make_float4(c[0][s], c[1][s], c[2][s], c[3][s]);
        *(float4*)(out + CO + (size_t)(seq0 + sq) * NH + ht * 4) = cv;
    }
}

extern "C" void kernel_launch(void* const* d_in, const int* in_sizes, int n_in,
                              void* d_out, int out_size) {
    const float* seq_p  = (const float*)d_in[0];
    const float* mask_p = (const float*)d_in[1];
    const float* W_ih   = (const float*)d_in[2];
    const float* W_hh   = (const float*)d_in[3];
    const float* b_ih   = (const float*)d_in[4];
    const float* b_hh   = (const float*)d_in[5];
    float* out = (float*)d_out;

    prep_kernel<<<64, 256>>>(W_ih, W_hh, b_ih, b_hh);

    cudaFuncSetAttribute(lstm_kernel, cudaFuncAttributeMaxDynamicSharedMemorySize, SMEM_BYTES);
    lstm_kernel<<<NSEQ / SPB, THREADS, SMEM_BYTES>>>(seq_p, mask_p, out);
}